// round 8
// baseline (speedup 1.0000x reference)
#include <cuda_runtime.h>

#define T_STEPS 512

// ---- packed f32x2 helpers (sm_100+ PTX) ----
__device__ __forceinline__ unsigned long long pack2(float lo, float hi){
    unsigned long long r;
    asm("mov.b64 %0, {%1, %2};" : "=l"(r) : "f"(lo), "f"(hi));
    return r;
}
__device__ __forceinline__ void ffma2(unsigned long long& acc, unsigned long long a, unsigned long long b){
    asm("fma.rn.f32x2 %0, %1, %2, %0;" : "+l"(acc) : "l"(a), "l"(b));
}
__device__ __forceinline__ float2 unpack2(unsigned long long v){
    float2 f;
    asm("mov.b64 {%0, %1}, %2;" : "=f"(f.x), "=f"(f.y) : "l"(v));
    return f;
}
// HW tanh (MUFU): 1 op, err ~2^-10.8. sigmoid(x)=0.5*tanh(x/2)+0.5.
__device__ __forceinline__ float tanh_a(float x){
    float r; asm("tanh.approx.f32 %0, %1;" : "=f"(r) : "f"(x)); return r;
}
__device__ __forceinline__ float sigmoid_a(float x){
    return fmaf(0.5f, tanh_a(0.5f * x), 0.5f);
}

// FOUR batch elements per warp, one warp per block, grid = B/4 = 512.
// -> ~3.46 blocks/SM, ~1 warp/SMSP UNIFORM: per-SMSP FMA issue (272 FFMA2
//    x rt2 = 544 cyc/step) identical to the old binding 2-warp SMSPs, but the
//    per-step serial tail (activations/STS/sync/LDS) is paid once per 4
//    batches and its four independent chains pipeline in-issue, instead of
//    two in-phase warps exposing their tails back to back.
// Lane j owns hidden unit j (gate rows j, 32+j, 64+j, 96+j) for all 4 batches.
// h staged per batch in smem slabs hs[m][32 steps][36] (36-float row stride ->
// rows 16B aligned -> LDS.128 broadcast; write row ts, read row ts-1).
// FC head deferred to once per 32 steps (transposed, lane j = step j).
__global__ void __launch_bounds__(32, 4) lstm_b4(
    const float* __restrict__ x,
    const float* __restrict__ W_ih,
    const float* __restrict__ W_hh,
    const float* __restrict__ b_ih,
    const float* __restrict__ b_hh,
    const float* __restrict__ W_fc,
    const float* __restrict__ b_fc,
    float* __restrict__ out,
    int B)
{
    const int lane = threadIdx.x;
    const int bb = blockIdx.x * 4;

    __shared__ __align__(16) float hs[4][32][36];
    __shared__ float wfcs[32];

    // ---- preload shared weights into registers (amortized over 512 steps) ----
    unsigned long long w2[4][16];   // 4 gate rows x 16 packed k-pairs = 128 regs
    unsigned long long wx2[4];
    float bias[4];
#pragma unroll
    for (int r = 0; r < 4; r++){
        const int row = r * 32 + lane;
        const float4* wr = reinterpret_cast<const float4*>(W_hh) + row * 8;
#pragma unroll
        for (int q = 0; q < 8; q++){
            float4 v = wr[q];
            w2[r][2*q]   = pack2(v.x, v.y);
            w2[r][2*q+1] = pack2(v.z, v.w);
        }
        wx2[r]  = pack2(W_ih[row*2 + 0], W_ih[row*2 + 1]);
        bias[r] = b_ih[row] + b_hh[row];
    }
    wfcs[lane] = W_fc[lane];
    const float bfc = b_fc[0];

    float c[4] = {0.f, 0.f, 0.f, 0.f};
#pragma unroll
    for (int m = 0; m < 4; m++)
        hs[m][31][lane] = 0.0f;     // h_{-1} = 0 (read by step 0)
    __syncwarp();

    const float2* xr[4];
#pragma unroll
    for (int m = 0; m < 4; m++){
        int bm = bb + m; if (bm >= B) bm = bb;   // safe dup for ragged B
        xr[m] = reinterpret_cast<const float2*>(x) + (size_t)bm * T_STEPS;
    }
    float2 xv[4];
#pragma unroll
    for (int m = 0; m < 4; m++) xv[m] = xr[m][0];

    for (int tb = 0; tb < T_STEPS / 32; tb++){
#pragma unroll 1
        for (int ts = 0; ts < 32; ts++){
            const int t  = (tb << 5) + ts;
            const int tn = (t + 1 < T_STEPS) ? (t + 1) : t;
            float2 xn[4];
#pragma unroll
            for (int m = 0; m < 4; m++) xn[m] = xr[m][tn];   // prefetch

            const int rp = (ts + 31) & 31;                   // row of h_{t-1}
            const ulonglong2* hp[4];
#pragma unroll
            for (int m = 0; m < 4; m++)
                hp[m] = reinterpret_cast<const ulonglong2*>(&hs[m][rp][0]);

            // init accumulators: lo = bias + x0*w0, hi = x1*w1
            unsigned long long a[4][4];
#pragma unroll
            for (int m = 0; m < 4; m++){
                unsigned long long xp = pack2(xv[m].x, xv[m].y);
#pragma unroll
                for (int r = 0; r < 4; r++){
                    a[m][r] = pack2(bias[r], 0.f);
                    ffma2(a[m][r], xp, wx2[r]);
                }
            }

            // MAC core: 256 packed FFMA2, 16 independent chains
#pragma unroll
            for (int q = 0; q < 8; q++){
                ulonglong2 v[4];
#pragma unroll
                for (int m = 0; m < 4; m++) v[m] = hp[m][q];
#pragma unroll
                for (int m = 0; m < 4; m++){
                    ffma2(a[m][0], v[m].x, w2[0][2*q]);
                    ffma2(a[m][1], v[m].x, w2[1][2*q]);
                    ffma2(a[m][2], v[m].x, w2[2][2*q]);
                    ffma2(a[m][3], v[m].x, w2[3][2*q]);
                }
#pragma unroll
                for (int m = 0; m < 4; m++){
                    ffma2(a[m][0], v[m].y, w2[0][2*q+1]);
                    ffma2(a[m][1], v[m].y, w2[1][2*q+1]);
                    ffma2(a[m][2], v[m].y, w2[2][2*q+1]);
                    ffma2(a[m][3], v[m].y, w2[3][2*q+1]);
                }
            }

            // gates for all 4 batches; unrolled so ptxas interleaves the four
            // independent MUFU/FMA chains (MUFU rt=8 pipelines across batches)
#pragma unroll
            for (int m = 0; m < 4; m++){
                float2 f0 = unpack2(a[m][0]), f1 = unpack2(a[m][1]);
                float2 f2 = unpack2(a[m][2]), f3 = unpack2(a[m][3]);
                const float ig = sigmoid_a(f0.x + f0.y);
                const float fg = sigmoid_a(f1.x + f1.y);
                const float gg = tanh_a   (f2.x + f2.y);
                const float og = sigmoid_a(f3.x + f3.y);
                c[m] = fmaf(fg, c[m], ig * gg);
                hs[m][ts][lane] = og * tanh_a(c[m]);
            }

            __syncwarp();   // publish h_t before next step reads it
#pragma unroll
            for (int m = 0; m < 4; m++) xv[m] = xn[m];
        }

        // ---- deferred FC head for this 32-step chunk ----
        // lane j computes out[t = tb*32 + j] = dot(h_t, wfc) + bfc
        float p[4] = {0.f, 0.f, 0.f, 0.f};
#pragma unroll
        for (int k = 0; k < 32; k++){
            const float w = wfcs[k];
#pragma unroll
            for (int m = 0; m < 4; m++)
                p[m] = fmaf(hs[m][lane][k], w, p[m]);
        }
        const int to = (tb << 5) + lane;
#pragma unroll
        for (int m = 0; m < 4; m++){
            const int bm = bb + m;
            if (bm < B) out[(size_t)bm * T_STEPS + to] = p[m] + bfc;
        }
        __syncwarp();   // FC reads complete before next chunk overwrites rows
    }
}

extern "C" void kernel_launch(void* const* d_in, const int* in_sizes, int n_in,
                              void* d_out, int out_size)
{
    const float* x   = (const float*)d_in[0];
    const float* Wih = (const float*)d_in[1];
    const float* Whh = (const float*)d_in[2];
    const float* bih = (const float*)d_in[3];
    const float* bhh = (const float*)d_in[4];
    const float* Wfc = (const float*)d_in[5];
    const float* bfc = (const float*)d_in[6];
    float* out = (float*)d_out;

    const int B = out_size / T_STEPS;      // OUT=1 -> out_size = B*T
    const int grid = (B + 3) / 4;          // four batch elements per warp
    lstm_b4<<<grid, 32>>>(x, Wih, Whh, bih, bhh, Wfc, bfc, out, B);
}

// round 9
// speedup vs baseline: 1.0006x; 1.0006x over previous
#include <cuda_runtime.h>

#define T_STEPS 512

// ---- packed f32x2 helpers (sm_100+ PTX) ----
__device__ __forceinline__ unsigned long long pack2(float lo, float hi){
    unsigned long long r;
    asm("mov.b64 %0, {%1, %2};" : "=l"(r) : "f"(lo), "f"(hi));
    return r;
}
__device__ __forceinline__ void ffma2(unsigned long long& acc, unsigned long long a, unsigned long long b){
    asm("fma.rn.f32x2 %0, %1, %2, %0;" : "+l"(acc) : "l"(a), "l"(b));
}
__device__ __forceinline__ float2 unpack2(unsigned long long v){
    float2 f;
    asm("mov.b64 {%0, %1}, %2;" : "=f"(f.x), "=f"(f.y) : "l"(v));
    return f;
}
// HW tanh (MUFU): 1 op, err ~2^-10.8. sigmoid(x)=0.5*tanh(x/2)+0.5.
__device__ __forceinline__ float tanh_a(float x){
    float r; asm("tanh.approx.f32 %0, %1;" : "=f"(r) : "f"(x)); return r;
}
__device__ __forceinline__ float sigmoid_a(float x){
    return fmaf(0.5f, tanh_a(0.5f * x), 0.5f);
}

// FOUR batch elements per warp, one warp per block, grid = B/4 = 512.
// -> ~3.46 blocks/SM, ~1 warp/SMSP UNIFORM: per-SMSP FMA issue (272 FFMA2
//    x rt2 = 544 cyc/step) identical to the old binding 2-warp SMSPs, but the
//    per-step serial tail (activations/STS/sync/LDS) is paid once per 4
//    batches and its four independent chains pipeline in-issue, instead of
//    two in-phase warps exposing their tails back to back.
// Lane j owns hidden unit j (gate rows j, 32+j, 64+j, 96+j) for all 4 batches.
// h staged per batch in smem slabs hs[m][32 steps][36] (36-float row stride ->
// rows 16B aligned -> LDS.128 broadcast; write row ts, read row ts-1).
// FC head deferred to once per 32 steps (transposed, lane j = step j).
__global__ void __launch_bounds__(32, 4) lstm_b4(
    const float* __restrict__ x,
    const float* __restrict__ W_ih,
    const float* __restrict__ W_hh,
    const float* __restrict__ b_ih,
    const float* __restrict__ b_hh,
    const float* __restrict__ W_fc,
    const float* __restrict__ b_fc,
    float* __restrict__ out,
    int B)
{
    const int lane = threadIdx.x;
    const int bb = blockIdx.x * 4;

    __shared__ __align__(16) float hs[4][32][36];
    __shared__ float wfcs[32];

    // ---- preload shared weights into registers (amortized over 512 steps) ----
    unsigned long long w2[4][16];   // 4 gate rows x 16 packed k-pairs = 128 regs
    unsigned long long wx2[4];
    float bias[4];
#pragma unroll
    for (int r = 0; r < 4; r++){
        const int row = r * 32 + lane;
        const float4* wr = reinterpret_cast<const float4*>(W_hh) + row * 8;
#pragma unroll
        for (int q = 0; q < 8; q++){
            float4 v = wr[q];
            w2[r][2*q]   = pack2(v.x, v.y);
            w2[r][2*q+1] = pack2(v.z, v.w);
        }
        wx2[r]  = pack2(W_ih[row*2 + 0], W_ih[row*2 + 1]);
        bias[r] = b_ih[row] + b_hh[row];
    }
    wfcs[lane] = W_fc[lane];
    const float bfc = b_fc[0];

    float c[4] = {0.f, 0.f, 0.f, 0.f};
#pragma unroll
    for (int m = 0; m < 4; m++)
        hs[m][31][lane] = 0.0f;     // h_{-1} = 0 (read by step 0)
    __syncwarp();

    const float2* xr[4];
#pragma unroll
    for (int m = 0; m < 4; m++){
        int bm = bb + m; if (bm >= B) bm = bb;   // safe dup for ragged B
        xr[m] = reinterpret_cast<const float2*>(x) + (size_t)bm * T_STEPS;
    }
    float2 xv[4];
#pragma unroll
    for (int m = 0; m < 4; m++) xv[m] = xr[m][0];

    for (int tb = 0; tb < T_STEPS / 32; tb++){
#pragma unroll 1
        for (int ts = 0; ts < 32; ts++){
            const int t  = (tb << 5) + ts;
            const int tn = (t + 1 < T_STEPS) ? (t + 1) : t;
            float2 xn[4];
#pragma unroll
            for (int m = 0; m < 4; m++) xn[m] = xr[m][tn];   // prefetch

            const int rp = (ts + 31) & 31;                   // row of h_{t-1}
            const ulonglong2* hp[4];
#pragma unroll
            for (int m = 0; m < 4; m++)
                hp[m] = reinterpret_cast<const ulonglong2*>(&hs[m][rp][0]);

            // init accumulators: lo = bias + x0*w0, hi = x1*w1
            unsigned long long a[4][4];
#pragma unroll
            for (int m = 0; m < 4; m++){
                unsigned long long xp = pack2(xv[m].x, xv[m].y);
#pragma unroll
                for (int r = 0; r < 4; r++){
                    a[m][r] = pack2(bias[r], 0.f);
                    ffma2(a[m][r], xp, wx2[r]);
                }
            }

            // MAC core: 256 packed FFMA2, 16 independent chains
#pragma unroll
            for (int q = 0; q < 8; q++){
                ulonglong2 v[4];
#pragma unroll
                for (int m = 0; m < 4; m++) v[m] = hp[m][q];
#pragma unroll
                for (int m = 0; m < 4; m++){
                    ffma2(a[m][0], v[m].x, w2[0][2*q]);
                    ffma2(a[m][1], v[m].x, w2[1][2*q]);
                    ffma2(a[m][2], v[m].x, w2[2][2*q]);
                    ffma2(a[m][3], v[m].x, w2[3][2*q]);
                }
#pragma unroll
                for (int m = 0; m < 4; m++){
                    ffma2(a[m][0], v[m].y, w2[0][2*q+1]);
                    ffma2(a[m][1], v[m].y, w2[1][2*q+1]);
                    ffma2(a[m][2], v[m].y, w2[2][2*q+1]);
                    ffma2(a[m][3], v[m].y, w2[3][2*q+1]);
                }
            }

            // gates for all 4 batches; unrolled so ptxas interleaves the four
            // independent MUFU/FMA chains (MUFU rt=8 pipelines across batches)
#pragma unroll
            for (int m = 0; m < 4; m++){
                float2 f0 = unpack2(a[m][0]), f1 = unpack2(a[m][1]);
                float2 f2 = unpack2(a[m][2]), f3 = unpack2(a[m][3]);
                const float ig = sigmoid_a(f0.x + f0.y);
                const float fg = sigmoid_a(f1.x + f1.y);
                const float gg = tanh_a   (f2.x + f2.y);
                const float og = sigmoid_a(f3.x + f3.y);
                c[m] = fmaf(fg, c[m], ig * gg);
                hs[m][ts][lane] = og * tanh_a(c[m]);
            }

            __syncwarp();   // publish h_t before next step reads it
#pragma unroll
            for (int m = 0; m < 4; m++) xv[m] = xn[m];
        }

        // ---- deferred FC head for this 32-step chunk ----
        // lane j computes out[t = tb*32 + j] = dot(h_t, wfc) + bfc
        float p[4] = {0.f, 0.f, 0.f, 0.f};
#pragma unroll
        for (int k = 0; k < 32; k++){
            const float w = wfcs[k];
#pragma unroll
            for (int m = 0; m < 4; m++)
                p[m] = fmaf(hs[m][lane][k], w, p[m]);
        }
        const int to = (tb << 5) + lane;
#pragma unroll
        for (int m = 0; m < 4; m++){
            const int bm = bb + m;
            if (bm < B) out[(size_t)bm * T_STEPS + to] = p[m] + bfc;
        }
        __syncwarp();   // FC reads complete before next chunk overwrites rows
    }
}

extern "C" void kernel_launch(void* const* d_in, const int* in_sizes, int n_in,
                              void* d_out, int out_size)
{
    const float* x   = (const float*)d_in[0];
    const float* Wih = (const float*)d_in[1];
    const float* Whh = (const float*)d_in[2];
    const float* bih = (const float*)d_in[3];
    const float* bhh = (const float*)d_in[4];
    const float* Wfc = (const float*)d_in[5];
    const float* bfc = (const float*)d_in[6];
    float* out = (float*)d_out;

    const int B = out_size / T_STEPS;      // OUT=1 -> out_size = B*T
    const int grid = (B + 3) / 4;          // four batch elements per warp
    lstm_b4<<<grid, 32>>>(x, Wih, Whh, bih, bhh, Wfc, bfc, out, B);
}